// round 17
// baseline (speedup 1.0000x reference)

#include <cuda_runtime.h>
#include <cstdint>

#define SEQ 1024
#define BSZ 16
#define DIM 512
#define NH 8
#define NN (SEQ*BSZ)          // 16384 nodes
#define E0 (NN*32)            // 524288 edges
#define ETOT (E0+NN)          // + self loops

// ---------------- scratch (device globals; accessed ONLY by symbol inside
// kernels — never passed as launch arguments from host code) ----------------
__device__ float g_xr[(size_t)NN*DIM];        // rnaf(perm(x))
__device__ float g_w0r[(size_t)DIM*DIM];      // rnaf(W0)
__device__ float g_h0[(size_t)NN*DIM];        // nodes @ W0 (pre-aggregation)
__device__ float g_h0act[(size_t)NN*DIM];     // layer0 output (elu)
__device__ float g_asrc0[NN*NH], g_adst0[NN*NH];
__device__ float g_asrc1[NN*NH], g_adst1[NN*NH];
__device__ float g_wsrc1[NH*DIM], g_wdst1[NH*DIM];
__device__ float g_agg1[(size_t)NN*NH*DIM];   // per-head aggregated inputs (tf32-rounded)
__device__ float g_wcat[(size_t)NH*DIM*DIM];  // tf32-rounded permuted W1 * 1/8
__device__ int g_cnt[NN], g_fill[NN], g_rowptr[NN+1], g_col[ETOT];

// ---------------- helpers ----------------
__device__ __forceinline__ float lrelu(float v){ return v > 0.f ? v : 0.2f*v; }
__device__ __forceinline__ float eluf(float v){ return v > 0.f ? v : expm1f(v); }
__device__ __forceinline__ float warpMax(float v){
    #pragma unroll
    for(int o=16;o;o>>=1) v = fmaxf(v, __shfl_xor_sync(0xffffffffu, v, o));
    return v;
}
__device__ __forceinline__ float warpSum(float v){
    #pragma unroll
    for(int o=16;o;o>>=1) v += __shfl_xor_sync(0xffffffffu, v, o);
    return v;
}
// tf32 round-to-nearest in pure C (no asm)
__device__ __forceinline__ float rnaf(float x){
    uint32_t u = __float_as_uint(x);
    u = (u + 0x1000u) & 0xFFFFE000u;
    return __uint_as_float(u);
}
#define MMA_TF32(C0,C1,C2,C3,A0,A1,A2,A3,B0,B1)                               \
    asm volatile(                                                             \
        "mma.sync.aligned.m16n8k8.row.col.f32.tf32.tf32.f32 "                 \
        "{%0,%1,%2,%3}, {%4,%5,%6,%7}, {%8,%9}, {%0,%1,%2,%3};\n"             \
        : "+f"(C0),"+f"(C1),"+f"(C2),"+f"(C3)                                 \
        : "r"(A0),"r"(A1),"r"(A2),"r"(A3), "r"(B0),"r"(B1))
__device__ __forceinline__ void cpa16(uint32_t s, const float* g){
    asm volatile("cp.async.cg.shared.global [%0], [%1], 16;\n" :: "r"(s), "l"(g));
}
__device__ __forceinline__ void cpa_commit(){ asm volatile("cp.async.commit_group;\n"); }
__device__ __forceinline__ void cpa_wait0(){ asm volatile("cp.async.wait_group 0;\n"); }

// ---------------- CSR build ----------------
__global__ void k_zero(){
    int i = blockIdx.x*blockDim.x + threadIdx.x;
    if(i < NN){ g_cnt[i]=0; g_fill[i]=0; }
}
__global__ void k_count(const int* __restrict__ edge){
    int e = blockIdx.x*blockDim.x + threadIdx.x;
    if(e >= ETOT) return;
    int d = (e < E0) ? edge[E0+e] : (e-E0);
    atomicAdd(&g_cnt[d], 1);
}
__global__ void k_scan(){
    __shared__ int sums[1024];
    int t = threadIdx.x;
    int base = t*16;
    int loc[16];
    int s = 0;
    #pragma unroll
    for(int i=0;i<16;i++){ loc[i] = s; s += g_cnt[base+i]; }
    sums[t] = s;
    __syncthreads();
    for(int off=1; off<1024; off<<=1){
        int v = 0;
        if(t >= off) v = sums[t-off];
        __syncthreads();
        if(t >= off) sums[t] += v;
        __syncthreads();
    }
    int pre = (t==0) ? 0 : sums[t-1];
    #pragma unroll
    for(int i=0;i<16;i++) g_rowptr[base+i] = pre + loc[i];
    if(t == 1023) g_rowptr[NN] = sums[1023];
}
__global__ void k_scatter(const int* __restrict__ edge){
    int e = blockIdx.x*blockDim.x + threadIdx.x;
    if(e >= ETOT) return;
    int s, d;
    if(e < E0){ s = edge[e]; d = edge[E0+e]; }
    else { s = e-E0; d = s; }
    int pos = g_rowptr[d] + atomicAdd(&g_fill[d], 1);
    g_col[pos] = s;
}

// ---------------- prep: rnaf'd operands for GEMM0 cp.async staging --------
__global__ void k_prepx(const float* __restrict__ x){
    int i = blockIdx.x*blockDim.x + threadIdx.x;    // < NN*DIM
    int n = i >> 9, k = i & 511;
    g_xr[i] = rnaf(x[(size_t)((n & (SEQ-1))*BSZ + (n >> 10))*DIM + k]);
}
__global__ void k_prepw0(const float* __restrict__ W0){
    int i = blockIdx.x*blockDim.x + threadIdx.x;    // < DIM*DIM
    g_w0r[i] = rnaf(W0[i]);
}

// =====================================================================
// cp.async double-buffered tf32 mma GEMM core macros (proven round 16).
//   As[2][128][20] (m-major, stride 20: banks 20q+s distinct)
//   Bs[2][16][136] (k-major, stride 136: banks 8s+q distinct)
// =====================================================================
#define DECLC(mi,ni) float c##mi##ni##_0=0.f, c##mi##ni##_1=0.f, \
                           c##mi##ni##_2=0.f, c##mi##ni##_3=0.f
#define NSTEP1(k8,ni) { \
    const int n_ = wn + ni*8 + (lane>>2); \
    const uint32_t b0_ = __float_as_uint(Bb[(k8)+(lane&3)    ][n_]); \
    const uint32_t b1_ = __float_as_uint(Bb[(k8)+(lane&3) + 4][n_]); \
    MMA_TF32(c0##ni##_0,c0##ni##_1,c0##ni##_2,c0##ni##_3, a00,a01,a02,a03, b0_,b1_); \
    MMA_TF32(c1##ni##_0,c1##ni##_1,c1##ni##_2,c1##ni##_3, a10,a11,a12,a13, b0_,b1_); }
#define KSTEP1(k8) { \
    const int r_  = wm + (lane>>2); \
    const int kk_ = (k8) + (lane&3); \
    const uint32_t a00 = __float_as_uint(Ab[r_   ][kk_  ]); \
    const uint32_t a01 = __float_as_uint(Ab[r_+ 8][kk_  ]); \
    const uint32_t a02 = __float_as_uint(Ab[r_   ][kk_+4]); \
    const uint32_t a03 = __float_as_uint(Ab[r_+ 8][kk_+4]); \
    const uint32_t a10 = __float_as_uint(Ab[r_+16][kk_  ]); \
    const uint32_t a11 = __float_as_uint(Ab[r_+24][kk_  ]); \
    const uint32_t a12 = __float_as_uint(Ab[r_+16][kk_+4]); \
    const uint32_t a13 = __float_as_uint(Ab[r_+24][kk_+4]); \
    NSTEP1(k8,0) NSTEP1(k8,1) NSTEP1(k8,2) NSTEP1(k8,3) \
    NSTEP1(k8,4) NSTEP1(k8,5) NSTEP1(k8,6) NSTEP1(k8,7) }

// body shared by both GEMMs: APTR/BPTR row bases, KD, A row stride = KD.
#define GEMM_CP_BODY(KD, APTR, BPTR, EPI_MACRO) \
    __shared__ float As[2][128][20]; \
    __shared__ float Bs[2][16][136]; \
    const int t = threadIdx.x; \
    const int lane = t & 31, warp = t >> 5; \
    const int row0 = blockIdx.y * 128; \
    const int col0 = blockIdx.x * 128; \
    const int wm = (warp >> 1) * 32; \
    const int wn = (warp & 1) * 64; \
    const int ar = t >> 2, ac4 = t & 3; \
    const float* aG = (APTR) + (size_t)(row0 + ar)*(KD) + ac4*4; \
    const int bkr = t >> 5, bc4 = t & 31; \
    const float* bG = (BPTR) + (size_t)bkr*DIM + col0 + bc4*4; \
    const uint32_t asB = (uint32_t)__cvta_generic_to_shared(&As[0][0][0]); \
    const uint32_t bsB = (uint32_t)__cvta_generic_to_shared(&Bs[0][0][0]); \
    const uint32_t aOff = (uint32_t)(ar*20 + ac4*4)*4; \
    const uint32_t bOff = (uint32_t)(bkr*136 + bc4*4)*4; \
    const uint32_t aBuf = 128*20*4, bBuf = 16*136*4; \
    const uint32_t aJ = 64*20*4, bJ = 8*136*4; \
    DECLC(0,0); DECLC(0,1); DECLC(0,2); DECLC(0,3); \
    DECLC(0,4); DECLC(0,5); DECLC(0,6); DECLC(0,7); \
    DECLC(1,0); DECLC(1,1); DECLC(1,2); DECLC(1,3); \
    DECLC(1,4); DECLC(1,5); DECLC(1,6); DECLC(1,7); \
    cpa16(asB + aOff,      aG); \
    cpa16(asB + aOff + aJ, aG + (size_t)64*(KD)); \
    cpa16(bsB + bOff,      bG); \
    cpa16(bsB + bOff + bJ, bG + (size_t)8*DIM); \
    cpa_commit(); \
    const int T = (KD)/16; \
    for(int kt=0; kt<T; kt++){ \
        cpa_wait0(); \
        __syncthreads(); \
        if(kt+1 < T){ \
            const int nb = (kt+1)&1; \
            const float* aN = aG + (kt+1)*16; \
            const float* bN = bG + (size_t)(kt+1)*16*DIM; \
            cpa16(asB + nb*aBuf + aOff,      aN); \
            cpa16(asB + nb*aBuf + aOff + aJ, aN + (size_t)64*(KD)); \
            cpa16(bsB + nb*bBuf + bOff,      bN); \
            cpa16(bsB + nb*bBuf + bOff + bJ, bN + (size_t)8*DIM); \
            cpa_commit(); \
        } \
        const int cb = kt&1; \
        const float (* __restrict__ Ab)[20]  = As[cb]; \
        const float (* __restrict__ Bb)[136] = Bs[cb]; \
        KSTEP1(0) \
        KSTEP1(8) \
        __syncthreads(); \
    } \
    EPI_MACRO(0,0) EPI_MACRO(0,1) EPI_MACRO(0,2) EPI_MACRO(0,3) \
    EPI_MACRO(0,4) EPI_MACRO(0,5) EPI_MACRO(0,6) EPI_MACRO(0,7) \
    EPI_MACRO(1,0) EPI_MACRO(1,1) EPI_MACRO(1,2) EPI_MACRO(1,3) \
    EPI_MACRO(1,4) EPI_MACRO(1,5) EPI_MACRO(1,6) EPI_MACRO(1,7)

#define EPI_G0(mi,ni) { \
    const int gr_ = row0 + wm + mi*16 + (lane>>2); \
    const int gc_ = col0 + wn + ni*8 + 2*(lane&3); \
    g_h0[(size_t)gr_*DIM + gc_    ] = c##mi##ni##_0; \
    g_h0[(size_t)gr_*DIM + gc_ + 1] = c##mi##ni##_1; \
    g_h0[(size_t)(gr_+8)*DIM + gc_    ] = c##mi##ni##_2; \
    g_h0[(size_t)(gr_+8)*DIM + gc_ + 1] = c##mi##ni##_3; }

#define EPI_G1(mi,ni) { \
    const int gr_ = row0 + wm + mi*16 + (lane>>2); \
    const int gc_ = col0 + wn + ni*8 + 2*(lane&3); \
    const float bx_ = b1[gc_], by_ = b1[gc_+1]; \
    out[(size_t)gr_*DIM + gc_    ] = eluf(c##mi##ni##_0 + bx_); \
    out[(size_t)gr_*DIM + gc_ + 1] = eluf(c##mi##ni##_1 + by_); \
    out[(size_t)(gr_+8)*DIM + gc_    ] = eluf(c##mi##ni##_2 + bx_); \
    out[(size_t)(gr_+8)*DIM + gc_ + 1] = eluf(c##mi##ni##_3 + by_); }

// GEMM0: g_h0 = g_xr @ g_w0r (pre-rounded by prep kernels)
__global__ void k_gemm0mma(){
    GEMM_CP_BODY(DIM, g_xr, g_w0r, EPI_G0)
}

// GEMM1: out = elu(g_agg1 @ g_wcat + b1)
__global__ void k_gemm1mma(const float* __restrict__ b1, float* __restrict__ out){
    GEMM_CP_BODY(NH*DIM, g_agg1, g_wcat, EPI_G1)
}

// ---------------- alpha0 ----------
__global__ void k_alpha0(const float* __restrict__ as0, const float* __restrict__ ad0){
    int n = blockIdx.x;
    int h = threadIdx.x >> 5, lane = threadIdx.x & 31;
    const float* hp = g_h0 + (size_t)n*DIM + h*64;
    float s=0.f, d=0.f;
    #pragma unroll
    for(int k=lane;k<64;k+=32){ float v=hp[k]; s += v*as0[h*64+k]; d += v*ad0[h*64+k]; }
    s = warpSum(s); d = warpSum(d);
    if(lane==0){ g_asrc0[n*NH+h]=s; g_adst0[n*NH+h]=d; }
}

// ---------------- aggregate0: 4-edge batched gather ----------
__global__ void k_agg0(const float* __restrict__ b0){
    __shared__ int cols_s[128];
    int d = blockIdx.x;
    int t = threadIdx.x;
    int h = t >> 5, lane = t & 31;
    int start = g_rowptr[d], deg = g_rowptr[d+1]-start;
    int ncache = deg < 128 ? deg : 128;
    for(int i=t;i<ncache;i+=256) cols_s[i] = g_col[start+i];
    __syncthreads();
    float adst = g_adst0[d*NH+h];
    float m = -1e30f;
    for(int i=lane;i<deg;i+=32){
        int s = (i<128) ? cols_s[i] : g_col[start+i];
        m = fmaxf(m, lrelu(g_asrc0[s*NH+h]+adst));
    }
    m = warpMax(m);
    float z = 0.f;
    for(int i=lane;i<deg;i+=32){
        int s = (i<128) ? cols_s[i] : g_col[start+i];
        z += __expf(lrelu(g_asrc0[s*NH+h]+adst)-m);
    }
    z = warpSum(z);
    float invz = 1.f/(z + 1e-16f);
    float acc0=0.f, acc1=0.f;
    for(int i0=0;i0<deg;i0+=4){
        float w[4]; const float* hp[4];
        #pragma unroll
        for(int c=0;c<4;c++){
            int i = i0 + c;
            if(i < deg){
                int s = (i<128) ? cols_s[i] : g_col[start+i];
                w[c] = __expf(lrelu(g_asrc0[s*NH+h]+adst)-m)*invz;
                hp[c] = g_h0 + (size_t)s*DIM + h*64;
            } else { w[c] = 0.f; hp[c] = g_h0; }
        }
        #pragma unroll
        for(int c=0;c<4;c++){
            acc0 += w[c]*hp[c][lane];
            acc1 += w[c]*hp[c][lane+32];
        }
    }
    int c = h*64 + lane;
    g_h0act[(size_t)d*DIM + c]      = eluf(acc0 + b0[c]);
    g_h0act[(size_t)d*DIM + c + 32] = eluf(acc1 + b0[c+32]);
}

// ---------------- weff1 ----------
__global__ void k_weff1(const float* __restrict__ W1, const float* __restrict__ as1,
                        const float* __restrict__ ad1){
    int w = blockIdx.x*8 + (threadIdx.x >> 5);
    int lane = threadIdx.x & 31;
    int h = w >> 9, k = w & 511;
    const float* wr = W1 + (size_t)k*(NH*DIM) + h*DIM;
    float s=0.f, d=0.f;
    for(int c=lane;c<DIM;c+=32){ float v=wr[c]; s += v*as1[h*DIM+c]; d += v*ad1[h*DIM+c]; }
    s = warpSum(s); d = warpSum(d);
    if(lane==0){ g_wsrc1[h*DIM+k]=s; g_wdst1[h*DIM+k]=d; }
}

// ---------------- alpha1 ----------
__global__ void k_alpha1(){
    int n = blockIdx.x;
    int h = threadIdx.x >> 5, lane = threadIdx.x & 31;
    const float* hp = g_h0act + (size_t)n*DIM;
    float s=0.f, d=0.f;
    for(int k=lane;k<DIM;k+=32){ float v=hp[k]; s += v*g_wsrc1[h*DIM+k]; d += v*g_wdst1[h*DIM+k]; }
    s = warpSum(s); d = warpSum(d);
    if(lane==0){ g_asrc1[n*NH+h]=s; g_adst1[n*NH+h]=d; }
}

// ---------------- aggregate1: chunked 4 edges per sync round -------------
__global__ void k_agg1(){
    __shared__ float v4[4][512];
    __shared__ float ws4[4][8];
    __shared__ float sm[8], sinvz[8], adst_s[8];
    __shared__ int cols_s[128];
    int d = blockIdx.x;
    int t = threadIdx.x;
    int warp = t >> 5, lane = t & 31;
    int start = g_rowptr[d], deg = g_rowptr[d+1]-start;
    int ncache = deg < 128 ? deg : 128;
    for(int i=t;i<ncache;i+=256) cols_s[i] = g_col[start+i];
    __syncthreads();
    {
        int h = warp;
        float adst = g_adst1[d*NH+h];
        float m = -1e30f;
        for(int i=lane;i<deg;i+=32){
            int s = (i<128) ? cols_s[i] : g_col[start+i];
            m = fmaxf(m, lrelu(g_asrc1[s*NH+h]+adst));
        }
        m = warpMax(m);
        float z = 0.f;
        for(int i=lane;i<deg;i+=32){
            int s = (i<128) ? cols_s[i] : g_col[start+i];
            z += __expf(lrelu(g_asrc1[s*NH+h]+adst)-m);
        }
        z = warpSum(z);
        if(lane==0){ sm[h]=m; sinvz[h]=1.f/(z+1e-16f); adst_s[h]=adst; }
    }
    __syncthreads();
    float acc[8][2];
    #pragma unroll
    for(int h=0;h<8;h++){ acc[h][0]=0.f; acc[h][1]=0.f; }
    for(int i0=0;i0<deg;i0+=4){
        #pragma unroll
        for(int c=0;c<4;c++){
            int i = i0 + c;
            if(i < deg){
                int s = (i<128) ? cols_s[i] : g_col[start+i];
                v4[c][t]     = g_h0act[(size_t)s*DIM + t];
                v4[c][t+256] = g_h0act[(size_t)s*DIM + t + 256];
            }
        }
        if(t < 32){
            int c = t >> 3, h = t & 7;
            int i = i0 + c;
            float w = 0.f;
            if(i < deg){
                int s = (i<128) ? cols_s[i] : g_col[start+i];
                w = __expf(lrelu(g_asrc1[s*NH+h]+adst_s[h])-sm[h])*sinvz[h];
            }
            ws4[c][h] = w;
        }
        __syncthreads();
        #pragma unroll
        for(int c=0;c<4;c++){
            float a0 = v4[c][t], a1 = v4[c][t+256];
            #pragma unroll
            for(int h=0;h<8;h++){
                float w = ws4[c][h];
                acc[h][0] += w*a0;
                acc[h][1] += w*a1;
            }
        }
        __syncthreads();
    }
    float* outp = g_agg1 + (size_t)d*(NH*DIM);
    #pragma unroll
    for(int h=0;h<8;h++){
        outp[h*DIM + t]       = rnaf(acc[h][0]);
        outp[h*DIM + t + 256] = rnaf(acc[h][1]);
    }
}

// ---------------- wcat ----------
__global__ void k_wcat(const float* __restrict__ W1){
    int i = blockIdx.x*blockDim.x + threadIdx.x;   // < 4096*512
    int c  = i & 511;
    int kk = i >> 9;          // h*512 + k
    int h = kk >> 9, k = kk & 511;
    g_wcat[i] = rnaf(W1[(size_t)k*(NH*DIM) + h*DIM + c] * 0.125f);
}

// ---------------- launch ----------------
extern "C" void kernel_launch(void* const* d_in, const int* in_sizes, int n_in,
                              void* d_out, int out_size){
    const float* x   = (const float*)d_in[0];
    const int*   edge= (const int*)  d_in[1];
    const float* W0  = (const float*)d_in[2];
    const float* as0 = (const float*)d_in[3];
    const float* ad0 = (const float*)d_in[4];
    const float* b0  = (const float*)d_in[5];
    const float* W1  = (const float*)d_in[6];
    const float* as1 = (const float*)d_in[7];
    const float* ad1 = (const float*)d_in[8];
    const float* b1  = (const float*)d_in[9];
    float* out = (float*)d_out;

    k_zero<<<(NN+255)/256, 256>>>();
    k_count<<<(ETOT+255)/256, 256>>>(edge);
    k_scan<<<1, 1024>>>();
    k_scatter<<<(ETOT+255)/256, 256>>>(edge);

    // layer 0
    k_prepx<<<(NN*DIM)/1024, 1024>>>(x);
    k_prepw0<<<(DIM*DIM)/1024, 1024>>>(W0);
    k_gemm0mma<<<dim3(DIM/128, NN/128), 256>>>();
    k_alpha0<<<NN, 256>>>(as0, ad0);
    k_agg0<<<NN, 256>>>(b0);

    // layer 1
    k_weff1<<<512, 256>>>(W1, as1, ad1);
    k_alpha1<<<NN, 256>>>();
    k_agg1<<<NN, 256>>>();
    k_wcat<<<(NH*DIM*DIM)/1024, 1024>>>(W1);
    k_gemm1mma<<<dim3(DIM/128, NN/128), 256>>>(b1, out);
}